// round 2
// baseline (speedup 1.0000x reference)
#include <cuda_runtime.h>
#include <cuda_bf16.h>
#include <math.h>

#define N_NODES 32768
#define E_DIM   512
#define H_HEADS 8
#define D_HEAD  64
#define NNZ_E   524288

// ---------------- scratch (static device globals; no allocations) ----------
__device__ float g_Q[(size_t)N_NODES * E_DIM];       // 64 MB
__device__ float g_K[(size_t)N_NODES * E_DIM];       // 64 MB
__device__ float g_logits[(size_t)NNZ_E * H_HEADS];  // 16 MB
__device__ int   g_rowptr[N_NODES + 1];

// ---------------- row_ptr via binary search (row_index is sorted) ----------
__global__ void rowptr_kernel(const int* __restrict__ row_index) {
    int r = blockIdx.x * blockDim.x + threadIdx.x;
    if (r > N_NODES) return;
    int lo = 0, hi = NNZ_E;
    while (lo < hi) {
        int mid = (lo + hi) >> 1;
        if (row_index[mid] < r) lo = mid + 1; else hi = mid;
    }
    g_rowptr[r] = lo;
}

// ---------------- SGEMM: C[m,n] = (sum_k A[m,k]*W[n,k] + bias[n]) * scale ---
// BM=BN=128, BK=8, 256 threads, 8x8 per-thread tile.
#define BM 128
#define BN 128
#define BK 8

__global__ __launch_bounds__(256, 2)
void sgemm_bias_kernel(const float* __restrict__ A,
                       const float* __restrict__ W,
                       const float* __restrict__ bias,
                       float* __restrict__ C,
                       float scale)
{
    __shared__ float As[BK][BM];
    __shared__ float Bs[BK][BN];

    const int bn = blockIdx.x;   // 0..3   (E/BN)
    const int bm = blockIdx.y;   // 0..255 (N/BM)
    const int tid = threadIdx.x;

    const int lrow = tid >> 1;          // 0..127
    const int lseg = (tid & 1) * 4;     // 0 or 4

    const float* Aptr = A + ((size_t)(bm * BM + lrow)) * E_DIM + lseg;
    const float* Wptr = W + ((size_t)(bn * BN + lrow)) * E_DIM + lseg;

    const int tx = tid & 15;   // 0..15
    const int ty = tid >> 4;   // 0..15

    float acc[8][8];
    #pragma unroll
    for (int i = 0; i < 8; i++)
        #pragma unroll
        for (int j = 0; j < 8; j++) acc[i][j] = 0.f;

    for (int k0 = 0; k0 < E_DIM; k0 += BK) {
        float4 av = *(const float4*)(Aptr + k0);
        float4 wv = *(const float4*)(Wptr + k0);
        As[lseg + 0][lrow] = av.x; As[lseg + 1][lrow] = av.y;
        As[lseg + 2][lrow] = av.z; As[lseg + 3][lrow] = av.w;
        Bs[lseg + 0][lrow] = wv.x; Bs[lseg + 1][lrow] = wv.y;
        Bs[lseg + 2][lrow] = wv.z; Bs[lseg + 3][lrow] = wv.w;
        __syncthreads();

        #pragma unroll
        for (int k = 0; k < BK; k++) {
            float4 a0 = *(const float4*)&As[k][ty * 8];
            float4 a1 = *(const float4*)&As[k][ty * 8 + 4];
            float4 b0 = *(const float4*)&Bs[k][tx * 8];
            float4 b1 = *(const float4*)&Bs[k][tx * 8 + 4];
            float ra[8] = {a0.x, a0.y, a0.z, a0.w, a1.x, a1.y, a1.z, a1.w};
            float rb[8] = {b0.x, b0.y, b0.z, b0.w, b1.x, b1.y, b1.z, b1.w};
            #pragma unroll
            for (int i = 0; i < 8; i++)
                #pragma unroll
                for (int j = 0; j < 8; j++)
                    acc[i][j] = fmaf(ra[i], rb[j], acc[i][j]);
        }
        __syncthreads();
    }

    // epilogue: (acc + bias) * scale
    #pragma unroll
    for (int i = 0; i < 8; i++) {
        int m = bm * BM + ty * 8 + i;
        float* crow = C + (size_t)m * E_DIM + bn * BN + tx * 8;
        #pragma unroll
        for (int j = 0; j < 8; j += 4) {
            int n = bn * BN + tx * 8 + j;
            float4 o;
            o.x = (acc[i][j + 0] + bias[n + 0]) * scale;
            o.y = (acc[i][j + 1] + bias[n + 1]) * scale;
            o.z = (acc[i][j + 2] + bias[n + 2]) * scale;
            o.w = (acc[i][j + 3] + bias[n + 3]) * scale;
            *(float4*)(crow + j) = o;
        }
    }
}

// ---------------- per-edge logits: warp per edge -----------------------------
// lane l covers floats [l*16, l*16+16) of the 512-float row; head = l>>2.
__global__ __launch_bounds__(256)
void edge_logits_kernel(const int* __restrict__ row_index,
                        const int* __restrict__ col_index,
                        const int* __restrict__ to_col_index,
                        const float* __restrict__ att_bias)
{
    int warp = (blockIdx.x * blockDim.x + threadIdx.x) >> 5;
    if (warp >= NNZ_E) return;
    const int lane = threadIdx.x & 31;
    const int e = warp;

    const int r  = row_index[e];
    const int c  = col_index[e];
    const int tc = to_col_index[c];

    const float4* qp = (const float4*)(g_Q + (size_t)r  * E_DIM + lane * 16);
    const float4* kp = (const float4*)(g_K + (size_t)tc * E_DIM + lane * 16);

    float acc = 0.f;
    #pragma unroll
    for (int i = 0; i < 4; i++) {
        float4 a = qp[i], b = kp[i];
        acc = fmaf(a.x, b.x, acc);
        acc = fmaf(a.y, b.y, acc);
        acc = fmaf(a.z, b.z, acc);
        acc = fmaf(a.w, b.w, acc);
    }
    acc += __shfl_xor_sync(0xFFFFFFFFu, acc, 1);
    acc += __shfl_xor_sync(0xFFFFFFFFu, acc, 2);

    int h = lane >> 2;
    if ((lane & 3) == 0) {
        g_logits[(size_t)e * H_HEADS + h] = acc + att_bias[(size_t)h * NNZ_E + e];
    }
}

// ---------------- per-row softmax + weighted position sums: warp per row -----
__global__ __launch_bounds__(256)
void row_reduce_kernel(const int* __restrict__ col_index,
                       const float* __restrict__ dist,
                       const float* __restrict__ pos,
                       const float* __restrict__ col_pos,
                       float* __restrict__ out)
{
    int r = (blockIdx.x * blockDim.x + threadIdx.x) >> 5;
    if (r >= N_NODES) return;
    const int lane = threadIdx.x & 31;

    const int s    = g_rowptr[r];
    const int eend = g_rowptr[r + 1];

    // pass 1: per-head max
    float mx[H_HEADS];
    #pragma unroll
    for (int h = 0; h < H_HEADS; h++) mx[h] = -INFINITY;

    for (int e = s + lane; e < eend; e += 32) {
        const float4* lp = (const float4*)(g_logits + (size_t)e * H_HEADS);
        float4 a = lp[0], b = lp[1];
        mx[0] = fmaxf(mx[0], a.x); mx[1] = fmaxf(mx[1], a.y);
        mx[2] = fmaxf(mx[2], a.z); mx[3] = fmaxf(mx[3], a.w);
        mx[4] = fmaxf(mx[4], b.x); mx[5] = fmaxf(mx[5], b.y);
        mx[6] = fmaxf(mx[6], b.z); mx[7] = fmaxf(mx[7], b.w);
    }
    #pragma unroll
    for (int h = 0; h < H_HEADS; h++) {
        #pragma unroll
        for (int o = 16; o > 0; o >>= 1)
            mx[h] = fmaxf(mx[h], __shfl_xor_sync(0xFFFFFFFFu, mx[h], o));
    }

    // pass 2: z = sum(p), s0 = sum(p*invd), v{xyz} = sum(p*invd*col_pos)
    float z[H_HEADS], s0[H_HEADS], vx[H_HEADS], vy[H_HEADS], vz[H_HEADS];
    #pragma unroll
    for (int h = 0; h < H_HEADS; h++) { z[h]=0.f; s0[h]=0.f; vx[h]=0.f; vy[h]=0.f; vz[h]=0.f; }

    for (int e = s + lane; e < eend; e += 32) {
        const float4* lp = (const float4*)(g_logits + (size_t)e * H_HEADS);
        float4 a = lp[0], b = lp[1];
        float lg[H_HEADS] = {a.x, a.y, a.z, a.w, b.x, b.y, b.z, b.w};
        float dd  = dist[e];
        float inv = (dd == 0.f) ? 0.f : (1.f / dd);
        int c = col_index[e];
        float cx = col_pos[(size_t)c * 3 + 0];
        float cy = col_pos[(size_t)c * 3 + 1];
        float cz = col_pos[(size_t)c * 3 + 2];
        #pragma unroll
        for (int h = 0; h < H_HEADS; h++) {
            float p = __expf(lg[h] - mx[h]);
            z[h]  += p;
            float w = p * inv;
            s0[h] += w;
            vx[h] = fmaf(w, cx, vx[h]);
            vy[h] = fmaf(w, cy, vy[h]);
            vz[h] = fmaf(w, cz, vz[h]);
        }
    }
    #pragma unroll
    for (int h = 0; h < H_HEADS; h++) {
        #pragma unroll
        for (int o = 16; o > 0; o >>= 1) {
            z[h]  += __shfl_xor_sync(0xFFFFFFFFu, z[h],  o);
            s0[h] += __shfl_xor_sync(0xFFFFFFFFu, s0[h], o);
            vx[h] += __shfl_xor_sync(0xFFFFFFFFu, vx[h], o);
            vy[h] += __shfl_xor_sync(0xFFFFFFFFu, vy[h], o);
            vz[h] += __shfl_xor_sync(0xFFFFFFFFu, vz[h], o);
        }
    }

    if (lane < H_HEADS) {
        int h = lane;
        float4 o = make_float4(0.f, 0.f, 0.f, 0.f);
        float Z = z[h];
        if (eend > s && Z > 0.f) {
            float invZ = 1.f / Z;
            float avg = s0[h] * invZ;
            float px = pos[(size_t)r * 3 + 0];
            float py = pos[(size_t)r * 3 + 1];
            float pz = pos[(size_t)r * 3 + 2];
            float dx = vx[h] * invZ - avg * px;
            float dy = vy[h] * invZ - avg * py;
            float dz = vz[h] * invZ - avg * pz;
            float nm = sqrtf(dx * dx + dy * dy + dz * dz);
            float dnm = fmaxf(nm, 1e-12f);
            o.x = dx / dnm; o.y = dy / dnm; o.z = dz / dnm; o.w = avg;
        }
        *(float4*)(out + (size_t)r * (H_HEADS * 4) + h * 4) = o;
    }
}

// ---------------- launch ----------------------------------------------------
extern "C" void kernel_launch(void* const* d_in, const int* in_sizes, int n_in,
                              void* d_out, int out_size)
{
    const float* x            = (const float*)d_in[0];
    const int*   row_index    = (const int*)  d_in[1];
    const int*   col_index    = (const int*)  d_in[2];
    const int*   to_col_index = (const int*)  d_in[3];
    const float* att_bias     = (const float*)d_in[4];
    const float* dist         = (const float*)d_in[5];
    const float* pos          = (const float*)d_in[6];
    const float* col_pos      = (const float*)d_in[7];
    const float* q_w          = (const float*)d_in[8];
    const float* q_b          = (const float*)d_in[9];
    const float* k_w          = (const float*)d_in[10];
    const float* k_b          = (const float*)d_in[11];
    float* out = (float*)d_out;

    float* Qg; cudaGetSymbolAddress((void**)&Qg, g_Q);
    float* Kg; cudaGetSymbolAddress((void**)&Kg, g_K);

    // row_ptr
    rowptr_kernel<<<(N_NODES + 1 + 255) / 256, 256>>>(row_index);

    // Q and K projections
    dim3 ggrid(E_DIM / BN, N_NODES / BM);
    sgemm_bias_kernel<<<ggrid, 256>>>(x, q_w, q_b, Qg, 0.125f);  // 1/sqrt(64)
    sgemm_bias_kernel<<<ggrid, 256>>>(x, k_w, k_b, Kg, 1.0f);

    // per-edge logits (warp per edge)
    edge_logits_kernel<<<NNZ_E / 8, 256>>>(row_index, col_index, to_col_index, att_bias);

    // per-row softmax + output (warp per row)
    row_reduce_kernel<<<N_NODES / 8, 256>>>(col_index, dist, pos, col_pos, out);
}

// round 3
// speedup vs baseline: 1.3674x; 1.3674x over previous
#include <cuda_runtime.h>
#include <cuda_bf16.h>
#include <math.h>
#include <stdint.h>

#define N_NODES 32768
#define E_DIM   512
#define H_HEADS 8
#define D_HEAD  64
#define NNZ_E   524288

// ---------------- scratch (static device globals; no allocations) ----------
__device__ float g_Q[(size_t)N_NODES * E_DIM];       // 64 MB
__device__ float g_K[(size_t)N_NODES * E_DIM];       // 64 MB
__device__ float g_logits[(size_t)NNZ_E * H_HEADS];  // 16 MB
__device__ int   g_rowptr[N_NODES + 1];

// ---------------- row_ptr via binary search (row_index is sorted) ----------
__global__ void rowptr_kernel(const int* __restrict__ row_index) {
    int r = blockIdx.x * blockDim.x + threadIdx.x;
    if (r > N_NODES) return;
    int lo = 0, hi = NNZ_E;
    while (lo < hi) {
        int mid = (lo + hi) >> 1;
        if (row_index[mid] < r) lo = mid + 1; else hi = mid;
    }
    g_rowptr[r] = lo;
}

// ---------------- TF32 tensor-core GEMM -------------------------------------
// C[m,n] = (sum_k A[m,k]*W[n,k] + bias[n]) * scale
// BM=128, BN=64, BK=32, 256 threads (8 warps as 4x2), mma.m16n8k8.tf32
#define GBM 128
#define GBN 64
#define GBK 32
#define A_PITCH 136   // 136 % 32 == 8 -> conflict-free fragment loads
#define B_PITCH 72    //  72 % 32 == 8

__device__ __forceinline__ float f2tf32(float x) {
    uint32_t u;
    asm("cvt.rna.tf32.f32 %0, %1;" : "=r"(u) : "f"(x));
    return __uint_as_float(u);
}

__global__ __launch_bounds__(256, 2)
void gemm_tf32_kernel(const float* __restrict__ A,
                      const float* __restrict__ W,
                      const float* __restrict__ bias,
                      float* __restrict__ C,
                      float scale)
{
    __shared__ float As[GBK][A_PITCH];
    __shared__ float Bs[GBK][B_PITCH];

    const int tid  = threadIdx.x;
    const int bm   = blockIdx.y;
    const int bn   = blockIdx.x;
    const int wid  = tid >> 5;
    const int lane = tid & 31;
    const int warp_m = wid >> 1;     // 0..3  -> 32 rows each
    const int warp_n = wid & 1;      // 0..1  -> 32 cols each
    const int groupID = lane >> 2;   // 0..7
    const int tid4    = lane & 3;    // 0..3

    float acc[2][4][4];
    #pragma unroll
    for (int i = 0; i < 2; i++)
        #pragma unroll
        for (int j = 0; j < 4; j++)
            #pragma unroll
            for (int c = 0; c < 4; c++) acc[i][j][c] = 0.f;

    // global load mapping
    const int arow  = tid & 127;          // 0..127
    const int acol0 = (tid >> 7) * 16;    // 0 or 16
    const int brow  = tid & 63;           // 0..63
    const int bcol0 = (tid >> 6) * 8;     // 0,8,16,24

    const float* Agp = A + (size_t)(bm * GBM + arow) * E_DIM + acol0;
    const float* Wgp = W + (size_t)(bn * GBN + brow) * E_DIM + bcol0;

    float4 pa[4], pb[2];
    #pragma unroll
    for (int i = 0; i < 4; i++) pa[i] = *(const float4*)(Agp + i * 4);
    #pragma unroll
    for (int i = 0; i < 2; i++) pb[i] = *(const float4*)(Wgp + i * 4);

    for (int k0 = 0; k0 < E_DIM; k0 += GBK) {
        // store tiles to smem (transposed, converted to tf32)
        #pragma unroll
        for (int i = 0; i < 4; i++) {
            As[acol0 + i * 4 + 0][arow] = f2tf32(pa[i].x);
            As[acol0 + i * 4 + 1][arow] = f2tf32(pa[i].y);
            As[acol0 + i * 4 + 2][arow] = f2tf32(pa[i].z);
            As[acol0 + i * 4 + 3][arow] = f2tf32(pa[i].w);
        }
        #pragma unroll
        for (int i = 0; i < 2; i++) {
            Bs[bcol0 + i * 4 + 0][brow] = f2tf32(pb[i].x);
            Bs[bcol0 + i * 4 + 1][brow] = f2tf32(pb[i].y);
            Bs[bcol0 + i * 4 + 2][brow] = f2tf32(pb[i].z);
            Bs[bcol0 + i * 4 + 3][brow] = f2tf32(pb[i].w);
        }
        __syncthreads();

        // prefetch next k-slab
        if (k0 + GBK < E_DIM) {
            #pragma unroll
            for (int i = 0; i < 4; i++) pa[i] = *(const float4*)(Agp + k0 + GBK + i * 4);
            #pragma unroll
            for (int i = 0; i < 2; i++) pb[i] = *(const float4*)(Wgp + k0 + GBK + i * 4);
        }

        #pragma unroll
        for (int ks = 0; ks < 4; ks++) {
            const int kb = ks * 8;
            uint32_t af[2][4], bf[4][2];
            #pragma unroll
            for (int i = 0; i < 2; i++) {
                int m = warp_m * 32 + i * 16;
                af[i][0] = __float_as_uint(As[kb + tid4    ][m + groupID    ]);
                af[i][1] = __float_as_uint(As[kb + tid4    ][m + groupID + 8]);
                af[i][2] = __float_as_uint(As[kb + tid4 + 4][m + groupID    ]);
                af[i][3] = __float_as_uint(As[kb + tid4 + 4][m + groupID + 8]);
            }
            #pragma unroll
            for (int j = 0; j < 4; j++) {
                int n = warp_n * 32 + j * 8;
                bf[j][0] = __float_as_uint(Bs[kb + tid4    ][n + groupID]);
                bf[j][1] = __float_as_uint(Bs[kb + tid4 + 4][n + groupID]);
            }
            #pragma unroll
            for (int i = 0; i < 2; i++)
                #pragma unroll
                for (int j = 0; j < 4; j++) {
                    asm volatile(
                        "mma.sync.aligned.m16n8k8.row.col.f32.tf32.tf32.f32 "
                        "{%0,%1,%2,%3}, {%4,%5,%6,%7}, {%8,%9}, {%0,%1,%2,%3};"
                        : "+f"(acc[i][j][0]), "+f"(acc[i][j][1]),
                          "+f"(acc[i][j][2]), "+f"(acc[i][j][3])
                        : "r"(af[i][0]), "r"(af[i][1]), "r"(af[i][2]), "r"(af[i][3]),
                          "r"(bf[j][0]), "r"(bf[j][1]));
                }
        }
        __syncthreads();
    }

    // epilogue: (acc + bias) * scale
    const int mbase = bm * GBM + warp_m * 32;
    const int nbase = bn * GBN + warp_n * 32;
    #pragma unroll
    for (int i = 0; i < 2; i++) {
        #pragma unroll
        for (int j = 0; j < 4; j++) {
            int row0 = mbase + i * 16 + groupID;
            int col  = nbase + j * 8 + tid4 * 2;
            float b0 = bias[col], b1 = bias[col + 1];
            float2 o0, o1;
            o0.x = (acc[i][j][0] + b0) * scale;
            o0.y = (acc[i][j][1] + b1) * scale;
            o1.x = (acc[i][j][2] + b0) * scale;
            o1.y = (acc[i][j][3] + b1) * scale;
            *(float2*)(C + (size_t)row0 * E_DIM + col)       = o0;
            *(float2*)(C + (size_t)(row0 + 8) * E_DIM + col) = o1;
        }
    }
}

// ---------------- per-edge logits: warp per ROW, Q in registers --------------
__global__ __launch_bounds__(256)
void edge_logits_rowwise(const int* __restrict__ col_index,
                         const int* __restrict__ to_col_index,
                         const float* __restrict__ att_bias)
{
    int r = (blockIdx.x * blockDim.x + threadIdx.x) >> 5;
    if (r >= N_NODES) return;
    const int lane = threadIdx.x & 31;

    const int s  = g_rowptr[r];
    const int e1 = g_rowptr[r + 1];
    if (s == e1) return;

    // lane l holds q floats [l*16, l*16+16)
    float4 q0, q1, q2, q3;
    {
        const float4* qp = (const float4*)(g_Q + (size_t)r * E_DIM + lane * 16);
        q0 = qp[0]; q1 = qp[1]; q2 = qp[2]; q3 = qp[3];
    }
    const int h = lane >> 2;
    const bool writer = (lane & 3) == 0;

    for (int base = s; base < e1; base += 32) {
        int myE = base + lane;
        int tc = 0;
        if (myE < e1) tc = to_col_index[col_index[myE]];
        int cnt = min(32, e1 - base);
        #pragma unroll 2
        for (int i = 0; i < cnt; i++) {
            int tci = __shfl_sync(0xFFFFFFFFu, tc, i);
            const float4* kp = (const float4*)(g_K + (size_t)tci * E_DIM + lane * 16);
            float4 k0 = kp[0], k1 = kp[1], k2 = kp[2], k3 = kp[3];
            float acc = 0.f;
            acc = fmaf(q0.x, k0.x, acc); acc = fmaf(q0.y, k0.y, acc);
            acc = fmaf(q0.z, k0.z, acc); acc = fmaf(q0.w, k0.w, acc);
            acc = fmaf(q1.x, k1.x, acc); acc = fmaf(q1.y, k1.y, acc);
            acc = fmaf(q1.z, k1.z, acc); acc = fmaf(q1.w, k1.w, acc);
            acc = fmaf(q2.x, k2.x, acc); acc = fmaf(q2.y, k2.y, acc);
            acc = fmaf(q2.z, k2.z, acc); acc = fmaf(q2.w, k2.w, acc);
            acc = fmaf(q3.x, k3.x, acc); acc = fmaf(q3.y, k3.y, acc);
            acc = fmaf(q3.z, k3.z, acc); acc = fmaf(q3.w, k3.w, acc);
            acc += __shfl_xor_sync(0xFFFFFFFFu, acc, 1);
            acc += __shfl_xor_sync(0xFFFFFFFFu, acc, 2);
            if (writer) {
                int e = base + i;
                g_logits[(size_t)e * H_HEADS + h] =
                    acc + att_bias[(size_t)h * NNZ_E + e];
            }
        }
    }
}

// ---------------- per-row softmax + weighted position sums: warp per row -----
__global__ __launch_bounds__(256)
void row_reduce_kernel(const int* __restrict__ col_index,
                       const float* __restrict__ dist,
                       const float* __restrict__ pos,
                       const float* __restrict__ col_pos,
                       float* __restrict__ out)
{
    int r = (blockIdx.x * blockDim.x + threadIdx.x) >> 5;
    if (r >= N_NODES) return;
    const int lane = threadIdx.x & 31;

    const int s    = g_rowptr[r];
    const int eend = g_rowptr[r + 1];

    // pass 1: per-head max
    float mx[H_HEADS];
    #pragma unroll
    for (int h = 0; h < H_HEADS; h++) mx[h] = -INFINITY;

    for (int e = s + lane; e < eend; e += 32) {
        const float4* lp = (const float4*)(g_logits + (size_t)e * H_HEADS);
        float4 a = lp[0], b = lp[1];
        mx[0] = fmaxf(mx[0], a.x); mx[1] = fmaxf(mx[1], a.y);
        mx[2] = fmaxf(mx[2], a.z); mx[3] = fmaxf(mx[3], a.w);
        mx[4] = fmaxf(mx[4], b.x); mx[5] = fmaxf(mx[5], b.y);
        mx[6] = fmaxf(mx[6], b.z); mx[7] = fmaxf(mx[7], b.w);
    }
    #pragma unroll
    for (int h = 0; h < H_HEADS; h++) {
        #pragma unroll
        for (int o = 16; o > 0; o >>= 1)
            mx[h] = fmaxf(mx[h], __shfl_xor_sync(0xFFFFFFFFu, mx[h], o));
    }

    float z[H_HEADS], s0[H_HEADS], vx[H_HEADS], vy[H_HEADS], vz[H_HEADS];
    #pragma unroll
    for (int h = 0; h < H_HEADS; h++) { z[h]=0.f; s0[h]=0.f; vx[h]=0.f; vy[h]=0.f; vz[h]=0.f; }

    for (int e = s + lane; e < eend; e += 32) {
        const float4* lp = (const float4*)(g_logits + (size_t)e * H_HEADS);
        float4 a = lp[0], b = lp[1];
        float lg[H_HEADS] = {a.x, a.y, a.z, a.w, b.x, b.y, b.z, b.w};
        float dd  = dist[e];
        float inv = (dd == 0.f) ? 0.f : (1.f / dd);
        int c = col_index[e];
        float cx = col_pos[(size_t)c * 3 + 0];
        float cy = col_pos[(size_t)c * 3 + 1];
        float cz = col_pos[(size_t)c * 3 + 2];
        #pragma unroll
        for (int h = 0; h < H_HEADS; h++) {
            float p = __expf(lg[h] - mx[h]);
            z[h]  += p;
            float w = p * inv;
            s0[h] += w;
            vx[h] = fmaf(w, cx, vx[h]);
            vy[h] = fmaf(w, cy, vy[h]);
            vz[h] = fmaf(w, cz, vz[h]);
        }
    }
    #pragma unroll
    for (int h = 0; h < H_HEADS; h++) {
        #pragma unroll
        for (int o = 16; o > 0; o >>= 1) {
            z[h]  += __shfl_xor_sync(0xFFFFFFFFu, z[h],  o);
            s0[h] += __shfl_xor_sync(0xFFFFFFFFu, s0[h], o);
            vx[h] += __shfl_xor_sync(0xFFFFFFFFu, vx[h], o);
            vy[h] += __shfl_xor_sync(0xFFFFFFFFu, vy[h], o);
            vz[h] += __shfl_xor_sync(0xFFFFFFFFu, vz[h], o);
        }
    }

    if (lane < H_HEADS) {
        int h = lane;
        float4 o = make_float4(0.f, 0.f, 0.f, 0.f);
        float Z = z[h];
        if (eend > s && Z > 0.f) {
            float invZ = 1.f / Z;
            float avg = s0[h] * invZ;
            float px = pos[(size_t)r * 3 + 0];
            float py = pos[(size_t)r * 3 + 1];
            float pz = pos[(size_t)r * 3 + 2];
            float dx = vx[h] * invZ - avg * px;
            float dy = vy[h] * invZ - avg * py;
            float dz = vz[h] * invZ - avg * pz;
            float nm = sqrtf(dx * dx + dy * dy + dz * dz);
            float dnm = fmaxf(nm, 1e-12f);
            o.x = dx / dnm; o.y = dy / dnm; o.z = dz / dnm; o.w = avg;
        }
        *(float4*)(out + (size_t)r * (H_HEADS * 4) + h * 4) = o;
    }
}

// ---------------- launch ----------------------------------------------------
extern "C" void kernel_launch(void* const* d_in, const int* in_sizes, int n_in,
                              void* d_out, int out_size)
{
    const float* x            = (const float*)d_in[0];
    const int*   row_index    = (const int*)  d_in[1];
    const int*   col_index    = (const int*)  d_in[2];
    const int*   to_col_index = (const int*)  d_in[3];
    const float* att_bias     = (const float*)d_in[4];
    const float* dist         = (const float*)d_in[5];
    const float* pos          = (const float*)d_in[6];
    const float* col_pos      = (const float*)d_in[7];
    const float* q_w          = (const float*)d_in[8];
    const float* q_b          = (const float*)d_in[9];
    const float* k_w          = (const float*)d_in[10];
    const float* k_b          = (const float*)d_in[11];
    float* out = (float*)d_out;

    float* Qg; cudaGetSymbolAddress((void**)&Qg, g_Q);
    float* Kg; cudaGetSymbolAddress((void**)&Kg, g_K);

    rowptr_kernel<<<(N_NODES + 1 + 255) / 256, 256>>>(row_index);

    dim3 ggrid(E_DIM / GBN, N_NODES / GBM);
    gemm_tf32_kernel<<<ggrid, 256>>>(x, q_w, q_b, Qg, 0.125f);  // 1/sqrt(64)
    gemm_tf32_kernel<<<ggrid, 256>>>(x, k_w, k_b, Kg, 1.0f);

    edge_logits_rowwise<<<N_NODES / 8, 256>>>(col_index, to_col_index, att_bias);

    row_reduce_kernel<<<N_NODES / 8, 256>>>(col_index, dist, pos, col_pos, out);
}

// round 4
// speedup vs baseline: 2.5081x; 1.8342x over previous
#include <cuda_runtime.h>
#include <cuda_bf16.h>
#include <math.h>
#include <stdint.h>

#define N_NODES 32768
#define E_DIM   512
#define H_HEADS 8
#define D_HEAD  64
#define NNZ_E   524288

// ---------------- scratch (static device globals; no allocations) ----------
__device__ float g_Q[(size_t)N_NODES * E_DIM];       // 64 MB
__device__ float g_K[(size_t)N_NODES * E_DIM];       // 64 MB
__device__ float g_logits[(size_t)NNZ_E * H_HEADS];  // 16 MB
__device__ int   g_rowptr[N_NODES + 1];

// ---------------- row_ptr via binary search (row_index is sorted) ----------
__global__ void rowptr_kernel(const int* __restrict__ row_index) {
    int r = blockIdx.x * blockDim.x + threadIdx.x;
    if (r > N_NODES) return;
    int lo = 0, hi = NNZ_E;
    while (lo < hi) {
        int mid = (lo + hi) >> 1;
        if (row_index[mid] < r) lo = mid + 1; else hi = mid;
    }
    g_rowptr[r] = lo;
}

// ---------------- fused TF32 tensor-core GEMM (Q & K), cp.async pipelined ----
// C[m,n] = (sum_k A[m,k]*W[n,k] + bias[n]) * scale
// BM=128, BN=128, BK=16, 2-stage cp.async, 256 threads (8 warps, 2x4),
// warp tile 64x32, mma.m16n8k8.tf32, smem pitch 20 (conflict-free).
#define GBM 128
#define GBN 128
#define GBK 16
#define KPITCH 20

__device__ __forceinline__ void cp_async16(uint32_t smem_addr, const void* gptr) {
    asm volatile("cp.async.cg.shared.global [%0], [%1], 16;\n"
                 :: "r"(smem_addr), "l"(gptr));
}
__device__ __forceinline__ void cp_commit() {
    asm volatile("cp.async.commit_group;\n");
}
__device__ __forceinline__ void cp_wait1() {
    asm volatile("cp.async.wait_group 1;\n");
}

__global__ __launch_bounds__(256, 2)
void gemm_tf32_fused(const float* __restrict__ A,
                     const float* __restrict__ Wq, const float* __restrict__ bq,
                     const float* __restrict__ Wk, const float* __restrict__ bk,
                     float* __restrict__ Cq, float* __restrict__ Ck)
{
    __shared__ float As[2][GBM * KPITCH];
    __shared__ float Bs[2][GBN * KPITCH];

    const int z = blockIdx.z;
    const float* W    = z ? Wk : Wq;
    const float* bias = z ? bk : bq;
    float*       C    = z ? Ck : Cq;
    const float scale = z ? 1.0f : 0.125f;   // q gets 1/sqrt(64)

    const int tid  = threadIdx.x;
    const int bm   = blockIdx.y;
    const int bn   = blockIdx.x;
    const int wid  = tid >> 5;
    const int lane = tid & 31;
    const int warp_m = wid >> 2;     // 0..1 -> 64 rows each
    const int warp_n = wid & 3;      // 0..3 -> 32 cols each
    const int g = lane >> 2;         // groupID 0..7
    const int t = lane & 3;          // 0..3

    // global->smem load mapping: 2 chunks of 16B for A and for B per thread
    const int c0   = tid;            // chunk ids c0, c0+256
    const int row0 = c0 >> 2;        // 0..63
    const int kc0  = (c0 & 3) * 4;   // 0,4,8,12
    const int row1 = (c0 + 256) >> 2; // 64..127
    const int kc1  = kc0;

    const float* Ag0 = A + (size_t)(bm * GBM + row0) * E_DIM + kc0;
    const float* Ag1 = A + (size_t)(bm * GBM + row1) * E_DIM + kc1;
    const float* Wg0 = W + (size_t)(bn * GBN + row0) * E_DIM + kc0;
    const float* Wg1 = W + (size_t)(bn * GBN + row1) * E_DIM + kc1;

    uint32_t sA = (uint32_t)__cvta_generic_to_shared(&As[0][0]);
    uint32_t sB = (uint32_t)__cvta_generic_to_shared(&Bs[0][0]);
    const uint32_t stageA = GBM * KPITCH * 4;
    const uint32_t stageB = GBN * KPITCH * 4;
    const uint32_t adst0 = (row0 * KPITCH + kc0) * 4;
    const uint32_t adst1 = (row1 * KPITCH + kc1) * 4;

    float acc[4][4][4];
    #pragma unroll
    for (int i = 0; i < 4; i++)
        #pragma unroll
        for (int j = 0; j < 4; j++)
            #pragma unroll
            for (int c = 0; c < 4; c++) acc[i][j][c] = 0.f;

    // prologue: stage 0 <- k0=0
    cp_async16(sA + adst0, Ag0);
    cp_async16(sA + adst1, Ag1);
    cp_async16(sB + adst0, Wg0);
    cp_async16(sB + adst1, Wg1);
    cp_commit();

    const int NIT = E_DIM / GBK;     // 32
    int cur = 0;

    for (int it = 0; it < NIT; it++) {
        if (it + 1 < NIT) {
            const int koff = (it + 1) * GBK;
            const uint32_t so = (cur ^ 1) ? 1u : 0u;
            cp_async16(sA + so * stageA + adst0, Ag0 + koff);
            cp_async16(sA + so * stageA + adst1, Ag1 + koff);
            cp_async16(sB + so * stageB + adst0, Wg0 + koff);
            cp_async16(sB + so * stageB + adst1, Wg1 + koff);
        }
        cp_commit();
        cp_wait1();
        __syncthreads();

        const float* __restrict__ Ac = &As[cur][0];
        const float* __restrict__ Bc = &Bs[cur][0];

        #pragma unroll
        for (int ks = 0; ks < 2; ks++) {
            const int kb = ks * 8;
            uint32_t af[4][4], bf[4][2];
            #pragma unroll
            for (int i = 0; i < 4; i++) {
                int m = warp_m * 64 + i * 16;
                af[i][0] = __float_as_uint(Ac[(m + g    ) * KPITCH + kb + t    ]);
                af[i][1] = __float_as_uint(Ac[(m + g + 8) * KPITCH + kb + t    ]);
                af[i][2] = __float_as_uint(Ac[(m + g    ) * KPITCH + kb + t + 4]);
                af[i][3] = __float_as_uint(Ac[(m + g + 8) * KPITCH + kb + t + 4]);
            }
            #pragma unroll
            for (int j = 0; j < 4; j++) {
                int n = warp_n * 32 + j * 8;
                bf[j][0] = __float_as_uint(Bc[(n + g) * KPITCH + kb + t    ]);
                bf[j][1] = __float_as_uint(Bc[(n + g) * KPITCH + kb + t + 4]);
            }
            #pragma unroll
            for (int i = 0; i < 4; i++)
                #pragma unroll
                for (int j = 0; j < 4; j++) {
                    asm volatile(
                        "mma.sync.aligned.m16n8k8.row.col.f32.tf32.tf32.f32 "
                        "{%0,%1,%2,%3}, {%4,%5,%6,%7}, {%8,%9}, {%0,%1,%2,%3};"
                        : "+f"(acc[i][j][0]), "+f"(acc[i][j][1]),
                          "+f"(acc[i][j][2]), "+f"(acc[i][j][3])
                        : "r"(af[i][0]), "r"(af[i][1]), "r"(af[i][2]), "r"(af[i][3]),
                          "r"(bf[j][0]), "r"(bf[j][1]));
                }
        }
        __syncthreads();
        cur ^= 1;
    }

    // epilogue: (acc + bias) * scale
    const int mbase = bm * GBM + warp_m * 64;
    const int nbase = bn * GBN + warp_n * 32;
    #pragma unroll
    for (int i = 0; i < 4; i++) {
        #pragma unroll
        for (int j = 0; j < 4; j++) {
            int row0e = mbase + i * 16 + g;
            int col   = nbase + j * 8 + t * 2;
            float b0 = bias[col], b1 = bias[col + 1];
            float2 o0, o1;
            o0.x = (acc[i][j][0] + b0) * scale;
            o0.y = (acc[i][j][1] + b1) * scale;
            o1.x = (acc[i][j][2] + b0) * scale;
            o1.y = (acc[i][j][3] + b1) * scale;
            *(float2*)(C + (size_t)row0e * E_DIM + col)       = o0;
            *(float2*)(C + (size_t)(row0e + 8) * E_DIM + col) = o1;
        }
    }
}

// ---------------- per-edge logits: warp per ROW, Q in registers --------------
__global__ __launch_bounds__(256)
void edge_logits_rowwise(const int* __restrict__ col_index,
                         const int* __restrict__ to_col_index,
                         const float* __restrict__ att_bias)
{
    int r = (blockIdx.x * blockDim.x + threadIdx.x) >> 5;
    if (r >= N_NODES) return;
    const int lane = threadIdx.x & 31;

    const int s  = g_rowptr[r];
    const int e1 = g_rowptr[r + 1];
    if (s == e1) return;

    float4 q0, q1, q2, q3;
    {
        const float4* qp = (const float4*)(g_Q + (size_t)r * E_DIM + lane * 16);
        q0 = qp[0]; q1 = qp[1]; q2 = qp[2]; q3 = qp[3];
    }
    const int h = lane >> 2;
    const bool writer = (lane & 3) == 0;

    for (int base = s; base < e1; base += 32) {
        int myE = base + lane;
        int tc = 0;
        if (myE < e1) tc = to_col_index[col_index[myE]];
        int cnt = min(32, e1 - base);
        #pragma unroll 2
        for (int i = 0; i < cnt; i++) {
            int tci = __shfl_sync(0xFFFFFFFFu, tc, i);
            const float4* kp = (const float4*)(g_K + (size_t)tci * E_DIM + lane * 16);
            float4 k0 = kp[0], k1 = kp[1], k2 = kp[2], k3 = kp[3];
            float acc = 0.f;
            acc = fmaf(q0.x, k0.x, acc); acc = fmaf(q0.y, k0.y, acc);
            acc = fmaf(q0.z, k0.z, acc); acc = fmaf(q0.w, k0.w, acc);
            acc = fmaf(q1.x, k1.x, acc); acc = fmaf(q1.y, k1.y, acc);
            acc = fmaf(q1.z, k1.z, acc); acc = fmaf(q1.w, k1.w, acc);
            acc = fmaf(q2.x, k2.x, acc); acc = fmaf(q2.y, k2.y, acc);
            acc = fmaf(q2.z, k2.z, acc); acc = fmaf(q2.w, k2.w, acc);
            acc = fmaf(q3.x, k3.x, acc); acc = fmaf(q3.y, k3.y, acc);
            acc = fmaf(q3.z, k3.z, acc); acc = fmaf(q3.w, k3.w, acc);
            acc += __shfl_xor_sync(0xFFFFFFFFu, acc, 1);
            acc += __shfl_xor_sync(0xFFFFFFFFu, acc, 2);
            if (writer) {
                int e = base + i;
                g_logits[(size_t)e * H_HEADS + h] =
                    acc + att_bias[(size_t)h * NNZ_E + e];
            }
        }
    }
}

// ---------------- per-row softmax + weighted position sums: warp per row -----
__global__ __launch_bounds__(256)
void row_reduce_kernel(const int* __restrict__ col_index,
                       const float* __restrict__ dist,
                       const float* __restrict__ pos,
                       const float* __restrict__ col_pos,
                       float* __restrict__ out)
{
    int r = (blockIdx.x * blockDim.x + threadIdx.x) >> 5;
    if (r >= N_NODES) return;
    const int lane = threadIdx.x & 31;

    const int s    = g_rowptr[r];
    const int eend = g_rowptr[r + 1];

    float mx[H_HEADS];
    #pragma unroll
    for (int h = 0; h < H_HEADS; h++) mx[h] = -INFINITY;

    for (int e = s + lane; e < eend; e += 32) {
        const float4* lp = (const float4*)(g_logits + (size_t)e * H_HEADS);
        float4 a = lp[0], b = lp[1];
        mx[0] = fmaxf(mx[0], a.x); mx[1] = fmaxf(mx[1], a.y);
        mx[2] = fmaxf(mx[2], a.z); mx[3] = fmaxf(mx[3], a.w);
        mx[4] = fmaxf(mx[4], b.x); mx[5] = fmaxf(mx[5], b.y);
        mx[6] = fmaxf(mx[6], b.z); mx[7] = fmaxf(mx[7], b.w);
    }
    #pragma unroll
    for (int h = 0; h < H_HEADS; h++) {
        #pragma unroll
        for (int o = 16; o > 0; o >>= 1)
            mx[h] = fmaxf(mx[h], __shfl_xor_sync(0xFFFFFFFFu, mx[h], o));
    }

    float z[H_HEADS], s0[H_HEADS], vx[H_HEADS], vy[H_HEADS], vz[H_HEADS];
    #pragma unroll
    for (int h = 0; h < H_HEADS; h++) { z[h]=0.f; s0[h]=0.f; vx[h]=0.f; vy[h]=0.f; vz[h]=0.f; }

    for (int e = s + lane; e < eend; e += 32) {
        const float4* lp = (const float4*)(g_logits + (size_t)e * H_HEADS);
        float4 a = lp[0], b = lp[1];
        float lg[H_HEADS] = {a.x, a.y, a.z, a.w, b.x, b.y, b.z, b.w};
        float dd  = dist[e];
        float inv = (dd == 0.f) ? 0.f : (1.f / dd);
        int c = col_index[e];
        float cx = col_pos[(size_t)c * 3 + 0];
        float cy = col_pos[(size_t)c * 3 + 1];
        float cz = col_pos[(size_t)c * 3 + 2];
        #pragma unroll
        for (int h = 0; h < H_HEADS; h++) {
            float p = __expf(lg[h] - mx[h]);
            z[h]  += p;
            float w = p * inv;
            s0[h] += w;
            vx[h] = fmaf(w, cx, vx[h]);
            vy[h] = fmaf(w, cy, vy[h]);
            vz[h] = fmaf(w, cz, vz[h]);
        }
    }
    #pragma unroll
    for (int h = 0; h < H_HEADS; h++) {
        #pragma unroll
        for (int o = 16; o > 0; o >>= 1) {
            z[h]  += __shfl_xor_sync(0xFFFFFFFFu, z[h],  o);
            s0[h] += __shfl_xor_sync(0xFFFFFFFFu, s0[h], o);
            vx[h] += __shfl_xor_sync(0xFFFFFFFFu, vx[h], o);
            vy[h] += __shfl_xor_sync(0xFFFFFFFFu, vy[h], o);
            vz[h] += __shfl_xor_sync(0xFFFFFFFFu, vz[h], o);
        }
    }

    if (lane < H_HEADS) {
        int h = lane;
        float4 o = make_float4(0.f, 0.f, 0.f, 0.f);
        float Z = z[h];
        if (eend > s && Z > 0.f) {
            float invZ = 1.f / Z;
            float avg = s0[h] * invZ;
            float px = pos[(size_t)r * 3 + 0];
            float py = pos[(size_t)r * 3 + 1];
            float pz = pos[(size_t)r * 3 + 2];
            float dx = vx[h] * invZ - avg * px;
            float dy = vy[h] * invZ - avg * py;
            float dz = vz[h] * invZ - avg * pz;
            float nm = sqrtf(dx * dx + dy * dy + dz * dz);
            float dnm = fmaxf(nm, 1e-12f);
            o.x = dx / dnm; o.y = dy / dnm; o.z = dz / dnm; o.w = avg;
        }
        *(float4*)(out + (size_t)r * (H_HEADS * 4) + h * 4) = o;
    }
}

// ---------------- launch ----------------------------------------------------
extern "C" void kernel_launch(void* const* d_in, const int* in_sizes, int n_in,
                              void* d_out, int out_size)
{
    const float* x            = (const float*)d_in[0];
    const int*   row_index    = (const int*)  d_in[1];
    const int*   col_index    = (const int*)  d_in[2];
    const int*   to_col_index = (const int*)  d_in[3];
    const float* att_bias     = (const float*)d_in[4];
    const float* dist         = (const float*)d_in[5];
    const float* pos          = (const float*)d_in[6];
    const float* col_pos      = (const float*)d_in[7];
    const float* q_w          = (const float*)d_in[8];
    const float* q_b          = (const float*)d_in[9];
    const float* k_w          = (const float*)d_in[10];
    const float* k_b          = (const float*)d_in[11];
    float* out = (float*)d_out;

    float* Qg; cudaGetSymbolAddress((void**)&Qg, g_Q);
    float* Kg; cudaGetSymbolAddress((void**)&Kg, g_K);

    rowptr_kernel<<<(N_NODES + 1 + 255) / 256, 256>>>(row_index);

    dim3 ggrid(E_DIM / GBN, N_NODES / GBM, 2);
    gemm_tf32_fused<<<ggrid, 256>>>(x, q_w, q_b, k_w, k_b, Qg, Kg);

    edge_logits_rowwise<<<N_NODES / 8, 256>>>(col_index, to_col_index, att_bias);

    row_reduce_kernel<<<N_NODES / 8, 256>>>(col_index, dist, pos, col_pos, out);
}

// round 5
// speedup vs baseline: 2.8550x; 1.1383x over previous
#include <cuda_runtime.h>
#include <cuda_bf16.h>
#include <math.h>
#include <stdint.h>

#define N_NODES 32768
#define E_DIM   512
#define H_HEADS 8
#define D_HEAD  64
#define NNZ_E   524288

// ---------------- scratch (static device globals; no allocations) ----------
__device__ float g_Q[(size_t)N_NODES * E_DIM];       // 64 MB
__device__ float g_K[(size_t)N_NODES * E_DIM];       // 64 MB
__device__ int   g_rowptr[N_NODES + 1];

// ---------------- row_ptr via binary search (row_index is sorted) ----------
__global__ void rowptr_kernel(const int* __restrict__ row_index) {
    int r = blockIdx.x * blockDim.x + threadIdx.x;
    if (r > N_NODES) return;
    int lo = 0, hi = NNZ_E;
    while (lo < hi) {
        int mid = (lo + hi) >> 1;
        if (row_index[mid] < r) lo = mid + 1; else hi = mid;
    }
    g_rowptr[r] = lo;
}

// ---------------- fused TF32 tensor-core GEMM (Q & K), cp.async pipelined ----
#define GBM 128
#define GBN 128
#define GBK 16
#define KPITCH 20

__device__ __forceinline__ void cp_async16(uint32_t smem_addr, const void* gptr) {
    asm volatile("cp.async.cg.shared.global [%0], [%1], 16;\n"
                 :: "r"(smem_addr), "l"(gptr));
}
__device__ __forceinline__ void cp_commit() {
    asm volatile("cp.async.commit_group;\n");
}
__device__ __forceinline__ void cp_wait1() {
    asm volatile("cp.async.wait_group 1;\n");
}

__global__ __launch_bounds__(256, 2)
void gemm_tf32_fused(const float* __restrict__ A,
                     const float* __restrict__ Wq, const float* __restrict__ bq,
                     const float* __restrict__ Wk, const float* __restrict__ bk,
                     float* __restrict__ Cq, float* __restrict__ Ck)
{
    __shared__ float As[2][GBM * KPITCH];
    __shared__ float Bs[2][GBN * KPITCH];

    const int z = blockIdx.z;
    const float* W    = z ? Wk : Wq;
    const float* bias = z ? bk : bq;
    float*       C    = z ? Ck : Cq;
    const float scale = z ? 1.0f : 0.125f;   // q gets 1/sqrt(64)

    const int tid  = threadIdx.x;
    const int bm   = blockIdx.y;
    const int bn   = blockIdx.x;
    const int wid  = tid >> 5;
    const int lane = tid & 31;
    const int warp_m = wid >> 2;     // 0..1 -> 64 rows each
    const int warp_n = wid & 3;      // 0..3 -> 32 cols each
    const int g = lane >> 2;         // groupID 0..7
    const int t = lane & 3;          // 0..3

    const int c0   = tid;
    const int row0 = c0 >> 2;
    const int kc0  = (c0 & 3) * 4;
    const int row1 = (c0 + 256) >> 2;

    const float* Ag0 = A + (size_t)(bm * GBM + row0) * E_DIM + kc0;
    const float* Ag1 = A + (size_t)(bm * GBM + row1) * E_DIM + kc0;
    const float* Wg0 = W + (size_t)(bn * GBN + row0) * E_DIM + kc0;
    const float* Wg1 = W + (size_t)(bn * GBN + row1) * E_DIM + kc0;

    uint32_t sA = (uint32_t)__cvta_generic_to_shared(&As[0][0]);
    uint32_t sB = (uint32_t)__cvta_generic_to_shared(&Bs[0][0]);
    const uint32_t stageA = GBM * KPITCH * 4;
    const uint32_t stageB = GBN * KPITCH * 4;
    const uint32_t adst0 = (row0 * KPITCH + kc0) * 4;
    const uint32_t adst1 = (row1 * KPITCH + kc0) * 4;

    float acc[4][4][4];
    #pragma unroll
    for (int i = 0; i < 4; i++)
        #pragma unroll
        for (int j = 0; j < 4; j++)
            #pragma unroll
            for (int c = 0; c < 4; c++) acc[i][j][c] = 0.f;

    cp_async16(sA + adst0, Ag0);
    cp_async16(sA + adst1, Ag1);
    cp_async16(sB + adst0, Wg0);
    cp_async16(sB + adst1, Wg1);
    cp_commit();

    const int NIT = E_DIM / GBK;
    int cur = 0;

    for (int it = 0; it < NIT; it++) {
        if (it + 1 < NIT) {
            const int koff = (it + 1) * GBK;
            const uint32_t so = (cur ^ 1) ? 1u : 0u;
            cp_async16(sA + so * stageA + adst0, Ag0 + koff);
            cp_async16(sA + so * stageA + adst1, Ag1 + koff);
            cp_async16(sB + so * stageB + adst0, Wg0 + koff);
            cp_async16(sB + so * stageB + adst1, Wg1 + koff);
        }
        cp_commit();
        cp_wait1();
        __syncthreads();

        const float* __restrict__ Ac = &As[cur][0];
        const float* __restrict__ Bc = &Bs[cur][0];

        #pragma unroll
        for (int ks = 0; ks < 2; ks++) {
            const int kb = ks * 8;
            uint32_t af[4][4], bf[4][2];
            #pragma unroll
            for (int i = 0; i < 4; i++) {
                int m = warp_m * 64 + i * 16;
                af[i][0] = __float_as_uint(Ac[(m + g    ) * KPITCH + kb + t    ]);
                af[i][1] = __float_as_uint(Ac[(m + g + 8) * KPITCH + kb + t    ]);
                af[i][2] = __float_as_uint(Ac[(m + g    ) * KPITCH + kb + t + 4]);
                af[i][3] = __float_as_uint(Ac[(m + g + 8) * KPITCH + kb + t + 4]);
            }
            #pragma unroll
            for (int j = 0; j < 4; j++) {
                int n = warp_n * 32 + j * 8;
                bf[j][0] = __float_as_uint(Bc[(n + g) * KPITCH + kb + t    ]);
                bf[j][1] = __float_as_uint(Bc[(n + g) * KPITCH + kb + t + 4]);
            }
            #pragma unroll
            for (int i = 0; i < 4; i++)
                #pragma unroll
                for (int j = 0; j < 4; j++) {
                    asm volatile(
                        "mma.sync.aligned.m16n8k8.row.col.f32.tf32.tf32.f32 "
                        "{%0,%1,%2,%3}, {%4,%5,%6,%7}, {%8,%9}, {%0,%1,%2,%3};"
                        : "+f"(acc[i][j][0]), "+f"(acc[i][j][1]),
                          "+f"(acc[i][j][2]), "+f"(acc[i][j][3])
                        : "r"(af[i][0]), "r"(af[i][1]), "r"(af[i][2]), "r"(af[i][3]),
                          "r"(bf[j][0]), "r"(bf[j][1]));
                }
        }
        __syncthreads();
        cur ^= 1;
    }

    const int mbase = bm * GBM + warp_m * 64;
    const int nbase = bn * GBN + warp_n * 32;
    #pragma unroll
    for (int i = 0; i < 4; i++) {
        #pragma unroll
        for (int j = 0; j < 4; j++) {
            int row0e = mbase + i * 16 + g;
            int col   = nbase + j * 8 + t * 2;
            float b0 = bias[col], b1 = bias[col + 1];
            float2 o0, o1;
            o0.x = (acc[i][j][0] + b0) * scale;
            o0.y = (acc[i][j][1] + b1) * scale;
            o1.x = (acc[i][j][2] + b0) * scale;
            o1.y = (acc[i][j][3] + b1) * scale;
            *(float2*)(C + (size_t)row0e * E_DIM + col)       = o0;
            *(float2*)(C + (size_t)(row0e + 8) * E_DIM + col) = o1;
        }
    }
}

// ---------------- fused edge logits + online softmax + output ---------------
// One warp per row. Lane l holds Q floats [l*16, l*16+16). Per edge, K row is
// loaded cooperatively; after xor-reduce every lane in quad g holds head-g's
// dot. Lanes 0..7 then run an online-softmax update for head==lane.
__global__ __launch_bounds__(256)
void fused_attn_kernel(const int* __restrict__ col_index,
                       const int* __restrict__ to_col_index,
                       const float* __restrict__ att_bias,
                       const float* __restrict__ dist,
                       const float* __restrict__ pos,
                       const float* __restrict__ col_pos,
                       float* __restrict__ out)
{
    int r = (blockIdx.x * blockDim.x + threadIdx.x) >> 5;
    if (r >= N_NODES) return;
    const int lane = threadIdx.x & 31;

    const int s  = g_rowptr[r];
    const int e1 = g_rowptr[r + 1];

    if (s == e1) {
        if (lane < H_HEADS)
            *(float4*)(out + (size_t)r * (H_HEADS * 4) + lane * 4) =
                make_float4(0.f, 0.f, 0.f, 0.f);
        return;
    }

    float4 q0, q1, q2, q3;
    {
        const float4* qp = (const float4*)(g_Q + (size_t)r * E_DIM + lane * 16);
        q0 = qp[0]; q1 = qp[1]; q2 = qp[2]; q3 = qp[3];
    }

    // online-softmax state (valid on lanes 0..7, head == lane)
    float m = -INFINITY, z = 0.f, s0 = 0.f, vx = 0.f, vy = 0.f, vz = 0.f;
    const size_t abase = (size_t)lane * NNZ_E;   // att_bias row for head==lane

    for (int base = s; base < e1; base += 32) {
        int myE = base + lane;
        int tc = 0; float dd = 0.f, cxl = 0.f, cyl = 0.f, czl = 0.f;
        if (myE < e1) {
            int c = col_index[myE];
            tc = to_col_index[c];
            dd = dist[myE];
            cxl = col_pos[(size_t)c * 3 + 0];
            cyl = col_pos[(size_t)c * 3 + 1];
            czl = col_pos[(size_t)c * 3 + 2];
        }
        int cnt = min(32, e1 - base);
        for (int i = 0; i < cnt; i++) {
            int tci = __shfl_sync(0xFFFFFFFFu, tc, i);
            const float4* kp = (const float4*)(g_K + (size_t)tci * E_DIM + lane * 16);
            float4 k0 = kp[0], k1 = kp[1], k2 = kp[2], k3 = kp[3];
            float acc = 0.f;
            acc = fmaf(q0.x, k0.x, acc); acc = fmaf(q0.y, k0.y, acc);
            acc = fmaf(q0.z, k0.z, acc); acc = fmaf(q0.w, k0.w, acc);
            acc = fmaf(q1.x, k1.x, acc); acc = fmaf(q1.y, k1.y, acc);
            acc = fmaf(q1.z, k1.z, acc); acc = fmaf(q1.w, k1.w, acc);
            acc = fmaf(q2.x, k2.x, acc); acc = fmaf(q2.y, k2.y, acc);
            acc = fmaf(q2.z, k2.z, acc); acc = fmaf(q2.w, k2.w, acc);
            acc = fmaf(q3.x, k3.x, acc); acc = fmaf(q3.y, k3.y, acc);
            acc = fmaf(q3.z, k3.z, acc); acc = fmaf(q3.w, k3.w, acc);
            acc += __shfl_xor_sync(0xFFFFFFFFu, acc, 1);
            acc += __shfl_xor_sync(0xFFFFFFFFu, acc, 2);

            // head h (=lane, for lane<8) value lives on lane 4h within quads
            float hv  = __shfl_sync(0xFFFFFFFFu, acc, (lane * 4) & 31);
            float ddi = __shfl_sync(0xFFFFFFFFu, dd,  i);
            float cxi = __shfl_sync(0xFFFFFFFFu, cxl, i);
            float cyi = __shfl_sync(0xFFFFFFFFu, cyl, i);
            float czi = __shfl_sync(0xFFFFFFFFu, czl, i);

            if (lane < H_HEADS) {
                float lg = hv + __ldg(att_bias + abase + (base + i));
                float mn = fmaxf(m, lg);
                float corr = __expf(m - mn);     // m==-inf first time -> 0
                float p    = __expf(lg - mn);
                float inv  = (ddi == 0.f) ? 0.f : (1.f / ddi);
                float w    = p * inv;
                z  = z  * corr + p;
                s0 = s0 * corr + w;
                vx = fmaf(vx, corr, w * cxi);
                vy = fmaf(vy, corr, w * cyi);
                vz = fmaf(vz, corr, w * czi);
                m = mn;
            }
        }
    }

    if (lane < H_HEADS) {
        float4 o = make_float4(0.f, 0.f, 0.f, 0.f);
        if (z > 0.f) {
            float invZ = 1.f / z;
            float avg = s0 * invZ;
            float px = pos[(size_t)r * 3 + 0];
            float py = pos[(size_t)r * 3 + 1];
            float pz = pos[(size_t)r * 3 + 2];
            float dx = vx * invZ - avg * px;
            float dy = vy * invZ - avg * py;
            float dz = vz * invZ - avg * pz;
            float nm = sqrtf(dx * dx + dy * dy + dz * dz);
            float dnm = fmaxf(nm, 1e-12f);
            o.x = dx / dnm; o.y = dy / dnm; o.z = dz / dnm; o.w = avg;
        }
        *(float4*)(out + (size_t)r * (H_HEADS * 4) + lane * 4) = o;
    }
}

// ---------------- launch ----------------------------------------------------
extern "C" void kernel_launch(void* const* d_in, const int* in_sizes, int n_in,
                              void* d_out, int out_size)
{
    const float* x            = (const float*)d_in[0];
    const int*   row_index    = (const int*)  d_in[1];
    const int*   col_index    = (const int*)  d_in[2];
    const int*   to_col_index = (const int*)  d_in[3];
    const float* att_bias     = (const float*)d_in[4];
    const float* dist         = (const float*)d_in[5];
    const float* pos          = (const float*)d_in[6];
    const float* col_pos      = (const float*)d_in[7];
    const float* q_w          = (const float*)d_in[8];
    const float* q_b          = (const float*)d_in[9];
    const float* k_w          = (const float*)d_in[10];
    const float* k_b          = (const float*)d_in[11];
    float* out = (float*)d_out;

    float* Qg; cudaGetSymbolAddress((void**)&Qg, g_Q);
    float* Kg; cudaGetSymbolAddress((void**)&Kg, g_K);

    rowptr_kernel<<<(N_NODES + 1 + 255) / 256, 256>>>(row_index);

    dim3 ggrid(E_DIM / GBN, N_NODES / GBM, 2);
    gemm_tf32_fused<<<ggrid, 256>>>(x, q_w, q_b, k_w, k_b, Qg, Kg);

    fused_attn_kernel<<<N_NODES / 8, 256>>>(col_index, to_col_index, att_bias,
                                            dist, pos, col_pos, out);
}

// round 6
// speedup vs baseline: 2.8898x; 1.0122x over previous
#include <cuda_runtime.h>
#include <cuda_bf16.h>
#include <math.h>
#include <stdint.h>

#define N_NODES 32768
#define E_DIM   512
#define H_HEADS 8
#define D_HEAD  64
#define NNZ_E   524288

// ---------------- scratch (static device globals; no allocations) ----------
__device__ float g_Q[(size_t)N_NODES * E_DIM];       // 64 MB
__device__ float g_K[(size_t)N_NODES * E_DIM];       // 64 MB
__device__ int   g_rowptr[N_NODES + 1];

// ---------------- row_ptr via boundary scatter (row_index is sorted) --------
__global__ void rowptr_scatter(const int* __restrict__ row_index) {
    int e = blockIdx.x * blockDim.x + threadIdx.x;
    if (e >= NNZ_E) return;
    int r = row_index[e];
    int prev = (e == 0) ? -1 : row_index[e - 1];
    for (int rr = prev + 1; rr <= r; rr++) g_rowptr[rr] = e;
    if (e == NNZ_E - 1) {
        for (int rr = r + 1; rr <= N_NODES; rr++) g_rowptr[rr] = NNZ_E;
    }
}

// ---------------- fused TF32 tensor-core GEMM (Q & K), cp.async pipelined ----
#define GBM 128
#define GBN 128
#define GBK 16
#define KPITCH 20

__device__ __forceinline__ void cp_async16(uint32_t smem_addr, const void* gptr) {
    asm volatile("cp.async.cg.shared.global [%0], [%1], 16;\n"
                 :: "r"(smem_addr), "l"(gptr));
}
__device__ __forceinline__ void cp_commit() {
    asm volatile("cp.async.commit_group;\n");
}
__device__ __forceinline__ void cp_wait1() {
    asm volatile("cp.async.wait_group 1;\n");
}

__global__ __launch_bounds__(256, 2)
void gemm_tf32_fused(const float* __restrict__ A,
                     const float* __restrict__ Wq, const float* __restrict__ bq,
                     const float* __restrict__ Wk, const float* __restrict__ bk,
                     float* __restrict__ Cq, float* __restrict__ Ck)
{
    __shared__ float As[2][GBM * KPITCH];
    __shared__ float Bs[2][GBN * KPITCH];

    const int z = blockIdx.z;
    const float* W    = z ? Wk : Wq;
    const float* bias = z ? bk : bq;
    float*       C    = z ? Ck : Cq;
    const float scale = z ? 1.0f : 0.125f;   // q gets 1/sqrt(64)

    const int tid  = threadIdx.x;
    const int bm   = blockIdx.y;
    const int bn   = blockIdx.x;
    const int wid  = tid >> 5;
    const int lane = tid & 31;
    const int warp_m = wid >> 2;     // 0..1 -> 64 rows each
    const int warp_n = wid & 3;      // 0..3 -> 32 cols each
    const int g = lane >> 2;         // groupID 0..7
    const int t = lane & 3;          // 0..3

    const int c0   = tid;
    const int row0 = c0 >> 2;
    const int kc0  = (c0 & 3) * 4;
    const int row1 = (c0 + 256) >> 2;

    const float* Ag0 = A + (size_t)(bm * GBM + row0) * E_DIM + kc0;
    const float* Ag1 = A + (size_t)(bm * GBM + row1) * E_DIM + kc0;
    const float* Wg0 = W + (size_t)(bn * GBN + row0) * E_DIM + kc0;
    const float* Wg1 = W + (size_t)(bn * GBN + row1) * E_DIM + kc0;

    uint32_t sA = (uint32_t)__cvta_generic_to_shared(&As[0][0]);
    uint32_t sB = (uint32_t)__cvta_generic_to_shared(&Bs[0][0]);
    const uint32_t stageA = GBM * KPITCH * 4;
    const uint32_t stageB = GBN * KPITCH * 4;
    const uint32_t adst0 = (row0 * KPITCH + kc0) * 4;
    const uint32_t adst1 = (row1 * KPITCH + kc0) * 4;

    float acc[4][4][4];
    #pragma unroll
    for (int i = 0; i < 4; i++)
        #pragma unroll
        for (int j = 0; j < 4; j++)
            #pragma unroll
            for (int c = 0; c < 4; c++) acc[i][j][c] = 0.f;

    cp_async16(sA + adst0, Ag0);
    cp_async16(sA + adst1, Ag1);
    cp_async16(sB + adst0, Wg0);
    cp_async16(sB + adst1, Wg1);
    cp_commit();

    const int NIT = E_DIM / GBK;
    int cur = 0;

    for (int it = 0; it < NIT; it++) {
        if (it + 1 < NIT) {
            const int koff = (it + 1) * GBK;
            const uint32_t so = (cur ^ 1) ? 1u : 0u;
            cp_async16(sA + so * stageA + adst0, Ag0 + koff);
            cp_async16(sA + so * stageA + adst1, Ag1 + koff);
            cp_async16(sB + so * stageB + adst0, Wg0 + koff);
            cp_async16(sB + so * stageB + adst1, Wg1 + koff);
        }
        cp_commit();
        cp_wait1();
        __syncthreads();

        const float* __restrict__ Ac = &As[cur][0];
        const float* __restrict__ Bc = &Bs[cur][0];

        #pragma unroll
        for (int ks = 0; ks < 2; ks++) {
            const int kb = ks * 8;
            uint32_t af[4][4], bf[4][2];
            #pragma unroll
            for (int i = 0; i < 4; i++) {
                int m = warp_m * 64 + i * 16;
                af[i][0] = __float_as_uint(Ac[(m + g    ) * KPITCH + kb + t    ]);
                af[i][1] = __float_as_uint(Ac[(m + g + 8) * KPITCH + kb + t    ]);
                af[i][2] = __float_as_uint(Ac[(m + g    ) * KPITCH + kb + t + 4]);
                af[i][3] = __float_as_uint(Ac[(m + g + 8) * KPITCH + kb + t + 4]);
            }
            #pragma unroll
            for (int j = 0; j < 4; j++) {
                int n = warp_n * 32 + j * 8;
                bf[j][0] = __float_as_uint(Bc[(n + g) * KPITCH + kb + t    ]);
                bf[j][1] = __float_as_uint(Bc[(n + g) * KPITCH + kb + t + 4]);
            }
            #pragma unroll
            for (int i = 0; i < 4; i++)
                #pragma unroll
                for (int j = 0; j < 4; j++) {
                    asm volatile(
                        "mma.sync.aligned.m16n8k8.row.col.f32.tf32.tf32.f32 "
                        "{%0,%1,%2,%3}, {%4,%5,%6,%7}, {%8,%9}, {%0,%1,%2,%3};"
                        : "+f"(acc[i][j][0]), "+f"(acc[i][j][1]),
                          "+f"(acc[i][j][2]), "+f"(acc[i][j][3])
                        : "r"(af[i][0]), "r"(af[i][1]), "r"(af[i][2]), "r"(af[i][3]),
                          "r"(bf[j][0]), "r"(bf[j][1]));
                }
        }
        __syncthreads();
        cur ^= 1;
    }

    const int mbase = bm * GBM + warp_m * 64;
    const int nbase = bn * GBN + warp_n * 32;
    #pragma unroll
    for (int i = 0; i < 4; i++) {
        #pragma unroll
        for (int j = 0; j < 4; j++) {
            int row0e = mbase + i * 16 + g;
            int col   = nbase + j * 8 + t * 2;
            float b0 = bias[col], b1 = bias[col + 1];
            float2 o0, o1;
            o0.x = (acc[i][j][0] + b0) * scale;
            o0.y = (acc[i][j][1] + b1) * scale;
            o1.x = (acc[i][j][2] + b0) * scale;
            o1.y = (acc[i][j][3] + b1) * scale;
            *(float2*)(C + (size_t)row0e * E_DIM + col)       = o0;
            *(float2*)(C + (size_t)(row0e + 8) * E_DIM + col) = o1;
        }
    }
}

// ---------------- fused edge logits + online softmax + output ---------------
// One warp per row. Lane l holds Q floats [l*16, l*16+16). Per edge the K row
// is loaded cooperatively with next-edge prefetch; 4 independent dot
// accumulators; lanes 0..7 run online softmax for head==lane.
__global__ __launch_bounds__(256)
void fused_attn_kernel(const int* __restrict__ col_index,
                       const int* __restrict__ to_col_index,
                       const float* __restrict__ att_bias,
                       const float* __restrict__ dist,
                       const float* __restrict__ pos,
                       const float* __restrict__ col_pos,
                       float* __restrict__ out)
{
    int r = (blockIdx.x * blockDim.x + threadIdx.x) >> 5;
    if (r >= N_NODES) return;
    const int lane = threadIdx.x & 31;

    const int s  = g_rowptr[r];
    const int e1 = g_rowptr[r + 1];

    if (s == e1) {
        if (lane < H_HEADS)
            *(float4*)(out + (size_t)r * (H_HEADS * 4) + lane * 4) =
                make_float4(0.f, 0.f, 0.f, 0.f);
        return;
    }

    float4 q0, q1, q2, q3;
    {
        const float4* qp = (const float4*)(g_Q + (size_t)r * E_DIM + lane * 16);
        q0 = qp[0]; q1 = qp[1]; q2 = qp[2]; q3 = qp[3];
    }

    // online-softmax state (valid on lanes 0..7, head == lane)
    float m = -INFINITY, z = 0.f, s0 = 0.f, vx = 0.f, vy = 0.f, vz = 0.f;
    const size_t abase = (size_t)lane * NNZ_E;   // att_bias row for head==lane

    for (int base = s; base < e1; base += 32) {
        int myE = base + lane;
        int tc = 0; float dd = 0.f, cxl = 0.f, cyl = 0.f, czl = 0.f;
        if (myE < e1) {
            int c = col_index[myE];
            tc = to_col_index[c];
            dd = dist[myE];
            cxl = col_pos[(size_t)c * 3 + 0];
            cyl = col_pos[(size_t)c * 3 + 1];
            czl = col_pos[(size_t)c * 3 + 2];
        }
        int cnt = min(32, e1 - base);

        // prefetch edge 0's K row
        int tci0 = __shfl_sync(0xFFFFFFFFu, tc, 0);
        const float4* kp0 = (const float4*)(g_K + (size_t)tci0 * E_DIM + lane * 16);
        float4 k0 = kp0[0], k1 = kp0[1], k2 = kp0[2], k3 = kp0[3];

        for (int i = 0; i < cnt; i++) {
            // prefetch next edge's K row while computing this one
            float4 n0 = k0, n1 = k1, n2 = k2, n3 = k3;
            if (i + 1 < cnt) {
                int tcn = __shfl_sync(0xFFFFFFFFu, tc, i + 1);
                const float4* np = (const float4*)(g_K + (size_t)tcn * E_DIM + lane * 16);
                n0 = np[0]; n1 = np[1]; n2 = np[2]; n3 = np[3];
            }

            // 4 independent accumulators -> short dependency chains
            float a0 = q0.x * k0.x, a1 = q1.x * k1.x, a2 = q2.x * k2.x, a3 = q3.x * k3.x;
            a0 = fmaf(q0.y, k0.y, a0); a1 = fmaf(q1.y, k1.y, a1);
            a2 = fmaf(q2.y, k2.y, a2); a3 = fmaf(q3.y, k3.y, a3);
            a0 = fmaf(q0.z, k0.z, a0); a1 = fmaf(q1.z, k1.z, a1);
            a2 = fmaf(q2.z, k2.z, a2); a3 = fmaf(q3.z, k3.z, a3);
            a0 = fmaf(q0.w, k0.w, a0); a1 = fmaf(q1.w, k1.w, a1);
            a2 = fmaf(q2.w, k2.w, a2); a3 = fmaf(q3.w, k3.w, a3);
            float acc = (a0 + a1) + (a2 + a3);
            acc += __shfl_xor_sync(0xFFFFFFFFu, acc, 1);
            acc += __shfl_xor_sync(0xFFFFFFFFu, acc, 2);

            // head h (=lane, for lane<8) value lives on lane 4h within quads
            float hv  = __shfl_sync(0xFFFFFFFFu, acc, (lane * 4) & 31);
            float ddi = __shfl_sync(0xFFFFFFFFu, dd,  i);
            float cxi = __shfl_sync(0xFFFFFFFFu, cxl, i);
            float cyi = __shfl_sync(0xFFFFFFFFu, cyl, i);
            float czi = __shfl_sync(0xFFFFFFFFu, czl, i);

            if (lane < H_HEADS) {
                float lg = hv + __ldg(att_bias + abase + (base + i));
                float mn = fmaxf(m, lg);
                float corr = __expf(m - mn);     // m==-inf first time -> 0
                float p    = __expf(lg - mn);
                float inv  = (ddi == 0.f) ? 0.f : (1.f / ddi);
                float w    = p * inv;
                z  = z  * corr + p;
                s0 = s0 * corr + w;
                vx = fmaf(vx, corr, w * cxi);
                vy = fmaf(vy, corr, w * cyi);
                vz = fmaf(vz, corr, w * czi);
                m = mn;
            }

            k0 = n0; k1 = n1; k2 = n2; k3 = n3;
        }
    }

    if (lane < H_HEADS) {
        float4 o = make_float4(0.f, 0.f, 0.f, 0.f);
        if (z > 0.f) {
            float invZ = 1.f / z;
            float avg = s0 * invZ;
            float px = pos[(size_t)r * 3 + 0];
            float py = pos[(size_t)r * 3 + 1];
            float pz = pos[(size_t)r * 3 + 2];
            float dx = vx * invZ - avg * px;
            float dy = vy * invZ - avg * py;
            float dz = vz * invZ - avg * pz;
            float nm = sqrtf(dx * dx + dy * dy + dz * dz);
            float dnm = fmaxf(nm, 1e-12f);
            o.x = dx / dnm; o.y = dy / dnm; o.z = dz / dnm; o.w = avg;
        }
        *(float4*)(out + (size_t)r * (H_HEADS * 4) + lane * 4) = o;
    }
}

// ---------------- launch ----------------------------------------------------
extern "C" void kernel_launch(void* const* d_in, const int* in_sizes, int n_in,
                              void* d_out, int out_size)
{
    const float* x            = (const float*)d_in[0];
    const int*   row_index    = (const int*)  d_in[1];
    const int*   col_index    = (const int*)  d_in[2];
    const int*   to_col_index = (const int*)  d_in[3];
    const float* att_bias     = (const float*)d_in[4];
    const float* dist         = (const float*)d_in[5];
    const float* pos          = (const float*)d_in[6];
    const float* col_pos      = (const float*)d_in[7];
    const float* q_w          = (const float*)d_in[8];
    const float* q_b          = (const float*)d_in[9];
    const float* k_w          = (const float*)d_in[10];
    const float* k_b          = (const float*)d_in[11];
    float* out = (float*)d_out;

    float* Qg; cudaGetSymbolAddress((void**)&Qg, g_Q);
    float* Kg; cudaGetSymbolAddress((void**)&Kg, g_K);

    rowptr_scatter<<<NNZ_E / 256, 256>>>(row_index);

    dim3 ggrid(E_DIM / GBN, N_NODES / GBM, 2);
    gemm_tf32_fused<<<ggrid, 256>>>(x, q_w, q_b, k_w, k_b, Qg, Kg);

    fused_attn_kernel<<<N_NODES / 8, 256>>>(col_index, to_col_index, att_bias,
                                            dist, pos, col_pos, out);
}

// round 7
// speedup vs baseline: 3.1134x; 1.0774x over previous
#include <cuda_runtime.h>
#include <cuda_bf16.h>
#include <math.h>
#include <stdint.h>

#define N_NODES 32768
#define E_DIM   512
#define H_HEADS 8
#define D_HEAD  64
#define NNZ_E   524288

// ---------------- scratch (static device globals; no allocations) ----------
__device__ float g_Q[(size_t)N_NODES * E_DIM];        // 64 MB
__device__ float g_K[(size_t)N_NODES * E_DIM];        // 64 MB
__device__ float g_biasT[(size_t)NNZ_E * H_HEADS];    // 16 MB, [e][h]
__device__ int   g_rowptr[N_NODES + 1];

// ---------------- row_ptr via boundary scatter (row_index is sorted) --------
__global__ void rowptr_scatter(const int* __restrict__ row_index) {
    int e = blockIdx.x * blockDim.x + threadIdx.x;
    if (e >= NNZ_E) return;
    int r = row_index[e];
    int prev = (e == 0) ? -1 : row_index[e - 1];
    for (int rr = prev + 1; rr <= r; rr++) g_rowptr[rr] = e;
    if (e == NNZ_E - 1) {
        for (int rr = r + 1; rr <= N_NODES; rr++) g_rowptr[rr] = NNZ_E;
    }
}

// ---------------- att_bias transpose: [H][NNZ] -> [NNZ][H] -------------------
__global__ void bias_transpose(const float* __restrict__ ab) {
    int e = blockIdx.x * blockDim.x + threadIdx.x;
    if (e >= NNZ_E) return;
    float4 v0, v1;
    v0.x = ab[(size_t)0 * NNZ_E + e];
    v0.y = ab[(size_t)1 * NNZ_E + e];
    v0.z = ab[(size_t)2 * NNZ_E + e];
    v0.w = ab[(size_t)3 * NNZ_E + e];
    v1.x = ab[(size_t)4 * NNZ_E + e];
    v1.y = ab[(size_t)5 * NNZ_E + e];
    v1.z = ab[(size_t)6 * NNZ_E + e];
    v1.w = ab[(size_t)7 * NNZ_E + e];
    float4* dst = (float4*)(g_biasT + (size_t)e * H_HEADS);
    dst[0] = v0; dst[1] = v1;
}

// ---------------- fused TF32 tensor-core GEMM (Q & K), cp.async pipelined ----
// BM=BN=128, BK=32, 2-stage dynamic-smem pipeline, 256 threads (8 warps 2x4),
// warp tile 64x32, mma.m16n8k8.tf32, pitch 36 (bank map 4g+t: conflict-free).
#define GBM 128
#define GBN 128
#define GBK 32
#define KPITCH 36
#define STAGE_FLOATS (GBM * KPITCH + GBN * KPITCH)   // 9216
#define GEMM_SMEM_BYTES (2 * STAGE_FLOATS * 4)        // 73728

__device__ __forceinline__ void cp_async16(uint32_t smem_addr, const void* gptr) {
    asm volatile("cp.async.cg.shared.global [%0], [%1], 16;\n"
                 :: "r"(smem_addr), "l"(gptr));
}
__device__ __forceinline__ void cp_commit() {
    asm volatile("cp.async.commit_group;\n");
}
__device__ __forceinline__ void cp_wait1() {
    asm volatile("cp.async.wait_group 1;\n");
}

__global__ __launch_bounds__(256, 2)
void gemm_tf32_fused(const float* __restrict__ A,
                     const float* __restrict__ Wq, const float* __restrict__ bq,
                     const float* __restrict__ Wk, const float* __restrict__ bk,
                     float* __restrict__ Cq, float* __restrict__ Ck)
{
    extern __shared__ float smem[];

    const int z = blockIdx.z;
    const float* W    = z ? Wk : Wq;
    const float* bias = z ? bk : bq;
    float*       C    = z ? Ck : Cq;
    const float scale = z ? 1.0f : 0.125f;   // q gets 1/sqrt(64)

    const int tid  = threadIdx.x;
    const int bm   = blockIdx.y;
    const int bn   = blockIdx.x;
    const int wid  = tid >> 5;
    const int lane = tid & 31;
    const int warp_m = wid >> 2;     // 0..1 -> 64 rows each
    const int warp_n = wid & 3;      // 0..3 -> 32 cols each
    const int g = lane >> 2;         // 0..7
    const int t = lane & 3;          // 0..3

    // global->smem: each thread loads 4 chunks of 16B for A and for B
    const int rA = tid >> 3;         // 0..31 (rows rA, rA+32, rA+64, rA+96)
    const int kc = (tid & 7) * 4;    // 0..28

    const float* Ag = A + (size_t)(bm * GBM + rA) * E_DIM + kc;
    const float* Wg = W + (size_t)(bn * GBN + rA) * E_DIM + kc;

    const uint32_t sbase = (uint32_t)__cvta_generic_to_shared(smem);
    const uint32_t aoff = (rA * KPITCH + kc) * 4;
    const uint32_t boff = (GBM * KPITCH + rA * KPITCH + kc) * 4;

    float acc[4][4][4];
    #pragma unroll
    for (int i = 0; i < 4; i++)
        #pragma unroll
        for (int j = 0; j < 4; j++)
            #pragma unroll
            for (int c = 0; c < 4; c++) acc[i][j][c] = 0.f;

    // prologue
    {
        const uint32_t sb = sbase;
        #pragma unroll
        for (int j = 0; j < 4; j++) {
            cp_async16(sb + aoff + j * (32 * KPITCH * 4), Ag + (size_t)j * 32 * E_DIM);
            cp_async16(sb + boff + j * (32 * KPITCH * 4), Wg + (size_t)j * 32 * E_DIM);
        }
    }
    cp_commit();

    const int NIT = E_DIM / GBK;     // 16
    int cur = 0;

    for (int it = 0; it < NIT; it++) {
        if (it + 1 < NIT) {
            const int koff = (it + 1) * GBK;
            const uint32_t sb = sbase + (uint32_t)(cur ^ 1) * (STAGE_FLOATS * 4);
            #pragma unroll
            for (int j = 0; j < 4; j++) {
                cp_async16(sb + aoff + j * (32 * KPITCH * 4),
                           Ag + koff + (size_t)j * 32 * E_DIM);
                cp_async16(sb + boff + j * (32 * KPITCH * 4),
                           Wg + koff + (size_t)j * 32 * E_DIM);
            }
        }
        cp_commit();
        cp_wait1();
        __syncthreads();

        const float* __restrict__ Ac = smem + cur * STAGE_FLOATS;
        const float* __restrict__ Bc = Ac + GBM * KPITCH;

        #pragma unroll
        for (int ks = 0; ks < 4; ks++) {
            const int kb = ks * 8;
            uint32_t af[4][4], bf[4][2];
            #pragma unroll
            for (int i = 0; i < 4; i++) {
                int m = warp_m * 64 + i * 16;
                af[i][0] = __float_as_uint(Ac[(m + g    ) * KPITCH + kb + t    ]);
                af[i][1] = __float_as_uint(Ac[(m + g + 8) * KPITCH + kb + t    ]);
                af[i][2] = __float_as_uint(Ac[(m + g    ) * KPITCH + kb + t + 4]);
                af[i][3] = __float_as_uint(Ac[(m + g + 8) * KPITCH + kb + t + 4]);
            }
            #pragma unroll
            for (int j = 0; j < 4; j++) {
                int n = warp_n * 32 + j * 8;
                bf[j][0] = __float_as_uint(Bc[(n + g) * KPITCH + kb + t    ]);
                bf[j][1] = __float_as_uint(Bc[(n + g) * KPITCH + kb + t + 4]);
            }
            #pragma unroll
            for (int i = 0; i < 4; i++)
                #pragma unroll
                for (int j = 0; j < 4; j++) {
                    asm volatile(
                        "mma.sync.aligned.m16n8k8.row.col.f32.tf32.tf32.f32 "
                        "{%0,%1,%2,%3}, {%4,%5,%6,%7}, {%8,%9}, {%0,%1,%2,%3};"
                        : "+f"(acc[i][j][0]), "+f"(acc[i][j][1]),
                          "+f"(acc[i][j][2]), "+f"(acc[i][j][3])
                        : "r"(af[i][0]), "r"(af[i][1]), "r"(af[i][2]), "r"(af[i][3]),
                          "r"(bf[j][0]), "r"(bf[j][1]));
                }
        }
        __syncthreads();
        cur ^= 1;
    }

    const int mbase = bm * GBM + warp_m * 64;
    const int nbase = bn * GBN + warp_n * 32;
    #pragma unroll
    for (int i = 0; i < 4; i++) {
        #pragma unroll
        for (int j = 0; j < 4; j++) {
            int row0e = mbase + i * 16 + g;
            int col   = nbase + j * 8 + t * 2;
            float b0 = bias[col], b1 = bias[col + 1];
            float2 o0, o1;
            o0.x = (acc[i][j][0] + b0) * scale;
            o0.y = (acc[i][j][1] + b1) * scale;
            o1.x = (acc[i][j][2] + b0) * scale;
            o1.y = (acc[i][j][3] + b1) * scale;
            *(float2*)(C + (size_t)row0e * E_DIM + col)       = o0;
            *(float2*)(C + (size_t)(row0e + 8) * E_DIM + col) = o1;
        }
    }
}

// ---------------- fused edge logits + softmax + output ----------------------
// One warp per row. No max-subtraction (logits are small; softmax is
// shift-invariant). Two edges per iteration with independent state sets
// (merge by addition) -> 2x ILP, 8 LDG.128 in flight.
__global__ __launch_bounds__(256)
void fused_attn_kernel(const int* __restrict__ col_index,
                       const int* __restrict__ to_col_index,
                       const float* __restrict__ dist,
                       const float* __restrict__ pos,
                       const float* __restrict__ col_pos,
                       float* __restrict__ out)
{
    int r = (blockIdx.x * blockDim.x + threadIdx.x) >> 5;
    if (r >= N_NODES) return;
    const int lane = threadIdx.x & 31;

    const int s  = g_rowptr[r];
    const int e1 = g_rowptr[r + 1];

    if (s == e1) {
        if (lane < H_HEADS)
            *(float4*)(out + (size_t)r * (H_HEADS * 4) + lane * 4) =
                make_float4(0.f, 0.f, 0.f, 0.f);
        return;
    }

    float4 q0, q1, q2, q3;
    {
        const float4* qp = (const float4*)(g_Q + (size_t)r * E_DIM + lane * 16);
        q0 = qp[0]; q1 = qp[1]; q2 = qp[2]; q3 = qp[3];
    }

    // two independent state sets (valid on lanes 0..7, head == lane)
    float zA = 0.f, sA = 0.f, vxA = 0.f, vyA = 0.f, vzA = 0.f;
    float zB = 0.f, sB = 0.f, vxB = 0.f, vyB = 0.f, vzB = 0.f;
    const int bshift = lane * 4;     // shfl source for head==lane

    for (int base = s; base < e1; base += 32) {
        int myE = base + lane;
        int tc = 0; float dd = 0.f, cxl = 0.f, cyl = 0.f, czl = 0.f;
        if (myE < e1) {
            int c = col_index[myE];
            tc = to_col_index[c];
            dd = dist[myE];
            cxl = col_pos[(size_t)c * 3 + 0];
            cyl = col_pos[(size_t)c * 3 + 1];
            czl = col_pos[(size_t)c * 3 + 2];
        }
        int cnt = min(32, e1 - base);

        int i = 0;
        for (; i + 2 <= cnt; i += 2) {
            int t0 = __shfl_sync(0xFFFFFFFFu, tc, i);
            int t1 = __shfl_sync(0xFFFFFFFFu, tc, i + 1);
            const float4* kpa = (const float4*)(g_K + (size_t)t0 * E_DIM + lane * 16);
            const float4* kpb = (const float4*)(g_K + (size_t)t1 * E_DIM + lane * 16);
            float4 a0 = kpa[0], a1 = kpa[1], a2 = kpa[2], a3 = kpa[3];
            float4 b0 = kpb[0], b1 = kpb[1], b2 = kpb[2], b3 = kpb[3];

            float d0 = q0.x * a0.x, d1 = q0.x * b0.x;
            d0 = fmaf(q0.y, a0.y, d0); d1 = fmaf(q0.y, b0.y, d1);
            d0 = fmaf(q0.z, a0.z, d0); d1 = fmaf(q0.z, b0.z, d1);
            d0 = fmaf(q0.w, a0.w, d0); d1 = fmaf(q0.w, b0.w, d1);
            d0 = fmaf(q1.x, a1.x, d0); d1 = fmaf(q1.x, b1.x, d1);
            d0 = fmaf(q1.y, a1.y, d0); d1 = fmaf(q1.y, b1.y, d1);
            d0 = fmaf(q1.z, a1.z, d0); d1 = fmaf(q1.z, b1.z, d1);
            d0 = fmaf(q1.w, a1.w, d0); d1 = fmaf(q1.w, b1.w, d1);
            d0 = fmaf(q2.x, a2.x, d0); d1 = fmaf(q2.x, b2.x, d1);
            d0 = fmaf(q2.y, a2.y, d0); d1 = fmaf(q2.y, b2.y, d1);
            d0 = fmaf(q2.z, a2.z, d0); d1 = fmaf(q2.z, b2.z, d1);
            d0 = fmaf(q2.w, a2.w, d0); d1 = fmaf(q2.w, b2.w, d1);
            d0 = fmaf(q3.x, a3.x, d0); d1 = fmaf(q3.x, b3.x, d1);
            d0 = fmaf(q3.y, a3.y, d0); d1 = fmaf(q3.y, b3.y, d1);
            d0 = fmaf(q3.z, a3.z, d0); d1 = fmaf(q3.z, b3.z, d1);
            d0 = fmaf(q3.w, a3.w, d0); d1 = fmaf(q3.w, b3.w, d1);

            d0 += __shfl_xor_sync(0xFFFFFFFFu, d0, 1);
            d1 += __shfl_xor_sync(0xFFFFFFFFu, d1, 1);
            d0 += __shfl_xor_sync(0xFFFFFFFFu, d0, 2);
            d1 += __shfl_xor_sync(0xFFFFFFFFu, d1, 2);

            float hv0 = __shfl_sync(0xFFFFFFFFu, d0, bshift & 31);
            float hv1 = __shfl_sync(0xFFFFFFFFu, d1, bshift & 31);
            float dd0 = __shfl_sync(0xFFFFFFFFu, dd,  i);
            float dd1 = __shfl_sync(0xFFFFFFFFu, dd,  i + 1);
            float cx0 = __shfl_sync(0xFFFFFFFFu, cxl, i);
            float cx1 = __shfl_sync(0xFFFFFFFFu, cxl, i + 1);
            float cy0 = __shfl_sync(0xFFFFFFFFu, cyl, i);
            float cy1 = __shfl_sync(0xFFFFFFFFu, cyl, i + 1);
            float cz0 = __shfl_sync(0xFFFFFFFFu, czl, i);
            float cz1 = __shfl_sync(0xFFFFFFFFu, czl, i + 1);

            if (lane < H_HEADS) {
                float lg0 = hv0 + g_biasT[(size_t)(base + i)     * H_HEADS + lane];
                float lg1 = hv1 + g_biasT[(size_t)(base + i + 1) * H_HEADS + lane];
                float p0 = __expf(lg0),            p1 = __expf(lg1);
                float i0 = (dd0 == 0.f) ? 0.f : (1.f / dd0);
                float i1 = (dd1 == 0.f) ? 0.f : (1.f / dd1);
                float w0 = p0 * i0,                w1 = p1 * i1;
                zA += p0;  zB += p1;
                sA += w0;  sB += w1;
                vxA = fmaf(w0, cx0, vxA);  vxB = fmaf(w1, cx1, vxB);
                vyA = fmaf(w0, cy0, vyA);  vyB = fmaf(w1, cy1, vyB);
                vzA = fmaf(w0, cz0, vzA);  vzB = fmaf(w1, cz1, vzB);
            }
        }
        // tail (at most one edge)
        if (i < cnt) {
            int t0 = __shfl_sync(0xFFFFFFFFu, tc, i);
            const float4* kpa = (const float4*)(g_K + (size_t)t0 * E_DIM + lane * 16);
            float4 a0 = kpa[0], a1 = kpa[1], a2 = kpa[2], a3 = kpa[3];
            float d0 = q0.x * a0.x;
            d0 = fmaf(q0.y, a0.y, d0); d0 = fmaf(q0.z, a0.z, d0); d0 = fmaf(q0.w, a0.w, d0);
            d0 = fmaf(q1.x, a1.x, d0); d0 = fmaf(q1.y, a1.y, d0);
            d0 = fmaf(q1.z, a1.z, d0); d0 = fmaf(q1.w, a1.w, d0);
            d0 = fmaf(q2.x, a2.x, d0); d0 = fmaf(q2.y, a2.y, d0);
            d0 = fmaf(q2.z, a2.z, d0); d0 = fmaf(q2.w, a2.w, d0);
            d0 = fmaf(q3.x, a3.x, d0); d0 = fmaf(q3.y, a3.y, d0);
            d0 = fmaf(q3.z, a3.z, d0); d0 = fmaf(q3.w, a3.w, d0);
            d0 += __shfl_xor_sync(0xFFFFFFFFu, d0, 1);
            d0 += __shfl_xor_sync(0xFFFFFFFFu, d0, 2);
            float hv0 = __shfl_sync(0xFFFFFFFFu, d0, bshift & 31);
            float dd0 = __shfl_sync(0xFFFFFFFFu, dd,  i);
            float cx0 = __shfl_sync(0xFFFFFFFFu, cxl, i);
            float cy0 = __shfl_sync(0xFFFFFFFFu, cyl, i);
            float cz0 = __shfl_sync(0xFFFFFFFFu, czl, i);
            if (lane < H_HEADS) {
                float lg0 = hv0 + g_biasT[(size_t)(base + i) * H_HEADS + lane];
                float p0 = __expf(lg0);
                float i0 = (dd0 == 0.f) ? 0.f : (1.f / dd0);
                float w0 = p0 * i0;
                zA += p0; sA += w0;
                vxA = fmaf(w0, cx0, vxA);
                vyA = fmaf(w0, cy0, vyA);
                vzA = fmaf(w0, cz0, vzA);
            }
        }
    }

    if (lane < H_HEADS) {
        float z  = zA + zB;
        float s0 = sA + sB;
        float vx = vxA + vxB, vy = vyA + vyB, vz = vzA + vzB;
        float4 o = make_float4(0.f, 0.f, 0.f, 0.f);
        if (z > 0.f) {
            float invZ = 1.f / z;
            float avg = s0 * invZ;
            float px = pos[(size_t)r * 3 + 0];
            float py = pos[(size_t)r * 3 + 1];
            float pz = pos[(size_t)r * 3 + 2];
            float dx = vx * invZ - avg * px;
            float dy = vy * invZ - avg * py;
            float dz = vz * invZ - avg * pz;
            float nm = sqrtf(dx * dx + dy * dy + dz * dz);
            float dnm = fmaxf(nm, 1e-12f);
            o.x = dx / dnm; o.y = dy / dnm; o.z = dz / dnm; o.w = avg;
        }
        *(float4*)(out + (size_t)r * (H_HEADS * 4) + lane * 4) = o;
    }
}

// ---------------- launch ----------------------------------------------------
extern "C" void kernel_launch(void* const* d_in, const int* in_sizes, int n_in,
                              void* d_out, int out_size)
{
    const float* x            = (const float*)d_in[0];
    const int*   row_index    = (const int*)  d_in[1];
    const int*   col_index    = (const int*)  d_in[2];
    const int*   to_col_index = (const int*)  d_in[3];
    const float* att_bias     = (const float*)d_in[4];
    const float* dist         = (const float*)d_in[5];
    const float* pos          = (const float*)d_in[6];
    const float* col_pos      = (const float*)d_in[7];
    const float* q_w          = (const float*)d_in[8];
    const float* q_b          = (const float*)d_in[9];
    const float* k_w          = (const float*)d_in[10];
    const float* k_b          = (const float*)d_in[11];
    float* out = (float*)d_out;

    float* Qg; cudaGetSymbolAddress((void**)&Qg, g_Q);
    float* Kg; cudaGetSymbolAddress((void**)&Kg, g_K);

    rowptr_scatter<<<NNZ_E / 256, 256>>>(row_index);
    bias_transpose<<<NNZ_E / 256, 256>>>(att_bias);

    cudaFuncSetAttribute(gemm_tf32_fused,
                         cudaFuncAttributeMaxDynamicSharedMemorySize,
                         GEMM_SMEM_BYTES);
    dim3 ggrid(E_DIM / GBN, N_NODES / GBM, 2);
    gemm_tf32_fused<<<ggrid, 256, GEMM_SMEM_BYTES>>>(x, q_w, q_b, k_w, k_b, Qg, Kg);

    fused_attn_kernel<<<N_NODES / 8, 256>>>(col_index, to_col_index,
                                            dist, pos, col_pos, out);
}